// round 12
// baseline (speedup 1.0000x reference)
#include <cuda_runtime.h>

#define BB   4
#define NN   512
#define FD   256
#define AD   256
#define DP   64
#define PD   128
#define ROWS (BB*NN)          /* 2048 */
#define NPAIR (BB*NN*NN)      /* 1048576 */
#define EPSF 1e-3f
#define SCAL 0.0625f          /* 1/sqrt(256) */

/* mega grid layout */
#define LNF_N    2048
#define BIAS_A   2048         /* bias chunk 1 */
#define T_N      128
#define BIAS_B   2048         /* bias chunk 2 */
#define MEGA_N   (LNF_N + BIAS_A + T_N + BIAS_B)   /* 6272 */

// ---------------- scratch (device globals; no allocation allowed) ----------
__device__ float d_Fn[ROWS*FD];
__device__ float d_M[FD*FD];         // Wq @ Wk^T
__device__ float d_T[ROWS*FD];       // Fn @ M
__device__ float d_vsum[ROWS];
__device__ float d_gw[DP];
__device__ float d_sgw;
__device__ float d_bconst;
__device__ float d_wvsum[FD];
__device__ float d_bias[NPAIR];
__device__ float d_Sa[NPAIR];        // split-K partial (K 0..127)
__device__ float d_Sb[NPAIR];        // split-K partial (K 128..255)
__device__ int   d_lnf_done;         // lnf completion counter (reset each call)

// ---------------- helpers ---------------------------------------------------
__device__ __forceinline__ float warp_sum(float v) {
    #pragma unroll
    for (int o = 16; o > 0; o >>= 1) v += __shfl_xor_sync(0xffffffffu, v, o);
    return v;
}
__device__ __forceinline__ float warp_max(float v) {
    #pragma unroll
    for (int o = 16; o > 0; o >>= 1) v = fmaxf(v, __shfl_xor_sync(0xffffffffu, v, o));
    return v;
}

// ---------------- K1: prep + mgemm  (grid 273 x 256) ------------------------
// blocks 0..15   : M = Wq @ Wk^T
// blocks 16..271 : wvsum[f] = sum_a Wv[f, a]
// block  272     : gw, sgw, bconst, reset d_lnf_done
__global__ void __launch_bounds__(256)
prep_mgemm_kernel(const float* __restrict__ Wq,
                  const float* __restrict__ Wk,
                  const float* __restrict__ Wv,
                  const float* __restrict__ gp,
                  const float* __restrict__ bp,
                  const float* __restrict__ Wpt,
                  const float* __restrict__ bpt,
                  const float* __restrict__ Wph) {
    int tid = threadIdx.x;

    if (blockIdx.x < 16) {
        __shared__ float As[16][68];
        __shared__ float Bs[16][68];
        int f0 = (blockIdx.x >> 2) * 64;
        int g0 = (blockIdx.x & 3) * 64;
        int lm = tid >> 2;
        int lk = (tid & 3) * 4;
        int ty = tid >> 4, tx = tid & 15;

        float acc[4][4] = {};
        for (int kt = 0; kt < AD; kt += 16) {
            float4 a = *(const float4*)&Wq[(f0 + lm)*AD + kt + lk];
            As[lk+0][lm] = a.x; As[lk+1][lm] = a.y;
            As[lk+2][lm] = a.z; As[lk+3][lm] = a.w;
            float4 c = *(const float4*)&Wk[(g0 + lm)*AD + kt + lk];
            Bs[lk+0][lm] = c.x; Bs[lk+1][lm] = c.y;
            Bs[lk+2][lm] = c.z; Bs[lk+3][lm] = c.w;
            __syncthreads();
            #pragma unroll
            for (int kf = 0; kf < 16; kf++) {
                float4 av = *(const float4*)&As[kf][ty*4];
                float4 bv = *(const float4*)&Bs[kf][tx*4];
                float aa[4] = {av.x, av.y, av.z, av.w};
                float bb[4] = {bv.x, bv.y, bv.z, bv.w};
                #pragma unroll
                for (int i = 0; i < 4; i++)
                    #pragma unroll
                    for (int j = 0; j < 4; j++)
                        acc[i][j] += aa[i] * bb[j];
            }
            __syncthreads();
        }
        #pragma unroll
        for (int i = 0; i < 4; i++)
            #pragma unroll
            for (int j = 0; j < 4; j++)
                d_M[(f0 + ty*4 + i)*FD + g0 + tx*4 + j] = acc[i][j];
    } else if (blockIdx.x < 272) {
        int f = blockIdx.x - 16;
        __shared__ float s_w[8];
        int w = tid >> 5, l = tid & 31;
        float s = warp_sum(Wv[f*AD + tid]);
        if (l == 0) s_w[w] = s;
        __syncthreads();
        if (tid == 0) {
            float acc = 0.f;
            #pragma unroll
            for (int i = 0; i < 8; i++) acc += s_w[i];
            d_wvsum[f] = acc;
        }
    } else {
        __shared__ float red[256];
        int c = tid >> 1;
        int j = tid & 1;
        float we = 0.f;
        if (tid < 128) {
            #pragma unroll
            for (int i = 0; i < 16; i++) {
                float4 a = *(const float4*)&Wpt[c*PD + j*64 + i*4];
                float4 b = *(const float4*)&Wph[j*64 + i*4];
                we += a.x*b.x + a.y*b.y + a.z*b.z + a.w*b.w;
            }
            we += __shfl_xor_sync(0xffffffffu, we, 1);
            if (j == 0) d_gw[c] = gp[c] * we;
        }
        float v_sgw = (tid < 128 && j == 0) ? gp[c] * we : 0.f;
        float v_bc  = (tid < 128 && j == 0) ? bp[c] * we : 0.f;
        float v_bpt = (tid < 128) ? bpt[tid] * Wph[tid] : 0.f;

        red[tid] = v_sgw; __syncthreads();
        #pragma unroll
        for (int o = 128; o > 0; o >>= 1) { if (tid < o) red[tid] += red[tid+o]; __syncthreads(); }
        if (tid == 0) d_sgw = red[0];
        __syncthreads();
        red[tid] = v_bc + v_bpt; __syncthreads();
        #pragma unroll
        for (int o = 128; o > 0; o >>= 1) { if (tid < o) red[tid] += red[tid+o]; __syncthreads(); }
        if (tid == 0) { d_bconst = red[0]; d_lnf_done = 0; }
    }
}

// ---------------- K2 mega: lnf | bias | T(guarded) | bias -------------------
__global__ void __launch_bounds__(256, 6)
mega_kernel(const float* __restrict__ F,
            const float* __restrict__ gf,
            const float* __restrict__ bf,
            const float* __restrict__ Dm) {
    int tid = threadIdx.x;
    int bx = blockIdx.x;

    if (bx < LNF_N) {
        // ---- LayerNorm(F) -> Fn, vsum ----
        __shared__ float s_a[8], s_b[8];
        int r = bx;
        int w = tid >> 5, l = tid & 31;
        float x = F[r*FD + tid];

        float sa = warp_sum(x);
        float sb = warp_sum(x*x);
        if (l == 0) { s_a[w] = sa; s_b[w] = sb; }
        __syncthreads();
        float ts = 0.f, tq = 0.f;
        #pragma unroll
        for (int i = 0; i < 8; i++) { ts += s_a[i]; tq += s_b[i]; }
        float mu = ts * (1.f/FD);
        float rstd = rsqrtf(tq * (1.f/FD) - mu*mu + EPSF);
        float fn = (x - mu) * rstd * gf[tid] + bf[tid];
        d_Fn[r*FD + tid] = fn;

        __syncthreads();
        float sv = warp_sum(fn * d_wvsum[tid]);
        if (l == 0) s_a[w] = sv;
        __syncthreads();
        if (tid == 0) {
            float acc = 0.f;
            #pragma unroll
            for (int i = 0; i < 8; i++) acc += s_a[i];
            d_vsum[r] = acc;
        }
        // signal completion (official threadfence-reduction pattern)
        __threadfence();
        __syncthreads();
        if (tid == 0) atomicAdd(&d_lnf_done, 1);
    } else if (bx < LNF_N + BIAS_A || bx >= LNF_N + BIAS_A + T_N) {
        // ---- bias sweep: 8 lanes per 64-float row ----
        int bias_id = (bx < LNF_N + BIAS_A) ? (bx - LNF_N)
                                            : (bx - LNF_N - T_N);
        int w = tid >> 5, l = tid & 31;
        int sub = l & 7;
        int rr  = l >> 3;

        float4 g0 = *(const float4*)&d_gw[sub*8];
        float4 g1 = *(const float4*)&d_gw[sub*8 + 4];
        float sgw = d_sgw, bconst = d_bconst;

        int rowbase = bias_id * 256 + w * 32 + rr;
        #pragma unroll
        for (int it = 0; it < 8; it++) {
            int row = rowbase + it * 4;
            const float4* p = (const float4*)&Dm[(size_t)row * DP];
            float4 c0 = __ldcs(p + sub*2);
            float4 c1 = __ldcs(p + sub*2 + 1);

            float s1 = (c0.x+c0.y+c0.z+c0.w) + (c1.x+c1.y+c1.z+c1.w);
            float s2 = c0.x*c0.x+c0.y*c0.y+c0.z*c0.z+c0.w*c0.w
                     + c1.x*c1.x+c1.y*c1.y+c1.z*c1.z+c1.w*c1.w;
            float s3 = c0.x*g0.x+c0.y*g0.y+c0.z*g0.z+c0.w*g0.w
                     + c1.x*g1.x+c1.y*g1.y+c1.z*g1.z+c1.w*g1.w;

            #pragma unroll
            for (int o = 1; o < 8; o <<= 1) {
                s1 += __shfl_xor_sync(0xffffffffu, s1, o);
                s2 += __shfl_xor_sync(0xffffffffu, s2, o);
                s3 += __shfl_xor_sync(0xffffffffu, s3, o);
            }
            if (sub == 0) {
                float mu = s1 * (1.f/DP);
                float var = s2 * (1.f/DP) - mu*mu;
                float rstd = rsqrtf(var + EPSF);
                d_bias[row] = rstd * (s3 - mu*sgw) + bconst;
            }
        }
    } else {
        // ---- T[2048 x 256] = Fn @ M  (waits for all lnf blocks) ----
        if (tid == 0) {
            while (atomicAdd(&d_lnf_done, 0) < LNF_N) { }
        }
        __syncthreads();

        __shared__ float As[16][68];
        __shared__ float Bs[16][68];
        int t2 = bx - LNF_N - BIAS_A;
        int bm = t2 & 31;
        int bn = t2 >> 5;
        int row0 = bm * 64;
        int n0   = bn * 64;

        int lm = tid >> 2;
        int lk = (tid & 3) * 4;
        int bk = tid >> 4;
        int bn4 = (tid & 15) * 4;
        int ty = tid >> 4, tx = tid & 15;

        float acc[4][4] = {};
        for (int kt = 0; kt < FD; kt += 16) {
            float4 a = *(const float4*)&d_Fn[(row0 + lm)*FD + kt + lk];
            As[lk+0][lm] = a.x; As[lk+1][lm] = a.y;
            As[lk+2][lm] = a.z; As[lk+3][lm] = a.w;
            float4 b = *(const float4*)&d_M[(kt + bk)*FD + n0 + bn4];
            Bs[bk][bn4+0] = b.x; Bs[bk][bn4+1] = b.y;
            Bs[bk][bn4+2] = b.z; Bs[bk][bn4+3] = b.w;
            __syncthreads();
            #pragma unroll
            for (int kf = 0; kf < 16; kf++) {
                float4 av = *(const float4*)&As[kf][ty*4];
                float4 bv = *(const float4*)&Bs[kf][tx*4];
                float aa[4] = {av.x, av.y, av.z, av.w};
                float bb[4] = {bv.x, bv.y, bv.z, bv.w};
                #pragma unroll
                for (int i = 0; i < 4; i++)
                    #pragma unroll
                    for (int j = 0; j < 4; j++)
                        acc[i][j] += aa[i] * bb[j];
            }
            __syncthreads();
        }
        #pragma unroll
        for (int i = 0; i < 4; i++) {
            int r = row0 + ty*4 + i;
            #pragma unroll
            for (int j = 0; j < 4; j++)
                d_T[r*FD + n0 + tx*4 + j] = acc[i][j];
        }
    }
}

// ---------------- K3: split-K S-GEMM, 128x128 block / 8x8 register tile -----
__global__ void __launch_bounds__(256)
s_gemm_kernel() {
    __shared__ float As[8][132];   // row stride 528B (16B-multiple)
    __shared__ float Bs[8][132];
    int z  = blockIdx.z;
    int b  = z >> 1;
    int half = z & 1;
    int q0 = blockIdx.y * 128;
    int k0 = blockIdx.x * 128;
    const float* A  = d_T  + b*NN*FD;
    const float* Bm = d_Fn + b*NN*FD;
    float* Sp = half ? d_Sb : d_Sa;

    int tid = threadIdx.x;
    int lrow = tid >> 1;            // 0..127
    int lk4  = (tid & 1) * 4;       // 0 or 4
    int ty = tid >> 4, tx = tid & 15;

    int kbase = half * 128;
    float acc[8][8] = {};

    float4 pa = *(const float4*)&A [(q0 + lrow)*FD + kbase + lk4];
    float4 pb = *(const float4*)&Bm[(k0 + lrow)*FD + kbase + lk4];

    for (int c = 0; c < 16; c++) {
        As[lk4+0][lrow] = pa.x; As[lk4+1][lrow] = pa.y;
        As[lk4+2][lrow] = pa.z; As[lk4+3][lrow] = pa.w;
        Bs[lk4+0][lrow] = pb.x; Bs[lk4+1][lrow] = pb.y;
        Bs[lk4+2][lrow] = pb.z; Bs[lk4+3][lrow] = pb.w;
        __syncthreads();
        if (c < 15) {
            int kt = kbase + (c + 1) * 8;
            pa = *(const float4*)&A [(q0 + lrow)*FD + kt + lk4];
            pb = *(const float4*)&Bm[(k0 + lrow)*FD + kt + lk4];
        }
        #pragma unroll
        for (int k = 0; k < 8; k++) {
            float a[8], bt[8];
            *(float4*)&a[0]  = *(const float4*)&As[k][ty*8];
            *(float4*)&a[4]  = *(const float4*)&As[k][ty*8 + 4];
            *(float4*)&bt[0] = *(const float4*)&Bs[k][tx*8];
            *(float4*)&bt[4] = *(const float4*)&Bs[k][tx*8 + 4];
            #pragma unroll
            for (int i = 0; i < 8; i++)
                #pragma unroll
                for (int j = 0; j < 8; j++)
                    acc[i][j] += a[i] * bt[j];
        }
        __syncthreads();
    }
    #pragma unroll
    for (int i = 0; i < 8; i++) {
        int q = q0 + ty*8 + i;
        int idx = (b*NN + q)*NN + k0 + tx*8;
        float4 o0, o1;
        o0.x = acc[i][0]; o0.y = acc[i][1]; o0.z = acc[i][2]; o0.w = acc[i][3];
        o1.x = acc[i][4]; o1.y = acc[i][5]; o1.z = acc[i][6]; o1.w = acc[i][7];
        *(float4*)&Sp[idx]     = o0;
        *(float4*)&Sp[idx + 4] = o1;
    }
}

// ---------------- K4: combine + softmax + dot with vsum (float2) ------------
__global__ void __launch_bounds__(256)
softmax_out_kernel(float* __restrict__ out) {
    __shared__ float s_a[8], s_b[8];
    int r = blockIdx.x;
    int b = r >> 9;
    int t = threadIdx.x;
    int w = t >> 5, l = t & 31;

    int i0 = r*NN + t*2;
    float2 a0 = *(const float2*)&d_Sa[i0];
    float2 b0 = *(const float2*)&d_Sb[i0];
    float2 bi = *(const float2*)&d_bias[i0];
    float2 vv = *(const float2*)&d_vsum[b*NN + t*2];
    float s0 = SCAL * (a0.x + b0.x + bi.x);
    float s1 = SCAL * (a0.y + b0.y + bi.y);

    float wm = warp_max(fmaxf(s0, s1));
    if (l == 0) s_a[w] = wm;
    __syncthreads();
    float m = s_a[0];
    #pragma unroll
    for (int i = 1; i < 8; i++) m = fmaxf(m, s_a[i]);

    float e0 = __expf(s0 - m), e1 = __expf(s1 - m);
    __syncthreads();
    float se = warp_sum(e0 + e1);
    float sv = warp_sum(e0*vv.x + e1*vv.y);
    if (l == 0) { s_a[w] = se; s_b[w] = sv; }
    __syncthreads();
    if (t == 0) {
        float tse = 0.f, tsv = 0.f;
        #pragma unroll
        for (int i = 0; i < 8; i++) { tse += s_a[i]; tsv += s_b[i]; }
        out[r] = tsv / tse;
    }
}

// ---------------- launch ----------------------------------------------------
extern "C" void kernel_launch(void* const* d_in, const int* in_sizes, int n_in,
                              void* d_out, int out_size) {
    const float* F   = (const float*)d_in[0];
    const float* Dm  = (const float*)d_in[1];
    const float* Wq  = (const float*)d_in[2];
    const float* Wk  = (const float*)d_in[3];
    const float* Wv  = (const float*)d_in[4];
    const float* gf  = (const float*)d_in[5];
    const float* bf  = (const float*)d_in[6];
    const float* gp  = (const float*)d_in[7];
    const float* bp  = (const float*)d_in[8];
    const float* Wpt = (const float*)d_in[9];
    const float* bpt = (const float*)d_in[10];
    const float* Wph = (const float*)d_in[11];
    float* out = (float*)d_out;

    prep_mgemm_kernel<<<273, 256>>>(Wq, Wk, Wv, gp, bp, Wpt, bpt, Wph);
    mega_kernel<<<MEGA_N, 256>>>(F, gf, bf, Dm);
    dim3 g3(4, 4, BB*2);
    s_gemm_kernel<<<g3, 256>>>();
    softmax_out_kernel<<<ROWS, 256>>>(out);
}

// round 13
// speedup vs baseline: 1.1733x; 1.1733x over previous
#include <cuda_runtime.h>

#define BB   4
#define NN   512
#define FD   256
#define AD   256
#define DP   64
#define PD   128
#define ROWS (BB*NN)          /* 2048 */
#define NPAIR (BB*NN*NN)      /* 1048576 */
#define EPSF 1e-3f
#define SCAL 0.0625f          /* 1/sqrt(256) */

#define BIAS_BLOCKS 4096      /* 1048576 rows / 256 rows per block */
#define T_TILES     128       /* (2048/64) * (256/64) */

// ---------------- scratch (device globals; no allocation allowed) ----------
__device__ float d_Fn[ROWS*FD];
__device__ float d_M[FD*FD];         // Wq @ Wk^T
__device__ float d_T[ROWS*FD];       // Fn @ M
__device__ float d_vsum[ROWS];
__device__ float d_gw[DP];
__device__ float d_sgw;
__device__ float d_bconst;
__device__ float d_wvsum[FD];
__device__ float d_bias[NPAIR];
__device__ float d_Sa[NPAIR];        // split-K partial (K 0..127)
__device__ float d_Sb[NPAIR];        // split-K partial (K 128..255)

// ---------------- helpers ---------------------------------------------------
__device__ __forceinline__ float warp_sum(float v) {
    #pragma unroll
    for (int o = 16; o > 0; o >>= 1) v += __shfl_xor_sync(0xffffffffu, v, o);
    return v;
}
__device__ __forceinline__ float warp_max(float v) {
    #pragma unroll
    for (int o = 16; o > 0; o >>= 1) v = fmaxf(v, __shfl_xor_sync(0xffffffffu, v, o));
    return v;
}

// ---------------- K1: prep (grid 257 x 128 threads) -------------------------
__global__ void __launch_bounds__(128)
prep_kernel(const float* __restrict__ Wv,
            const float* __restrict__ gp,
            const float* __restrict__ bp,
            const float* __restrict__ Wpt,
            const float* __restrict__ bpt,
            const float* __restrict__ Wph) {
    int t = threadIdx.x;
    int w = t >> 5, l = t & 31;

    if (blockIdx.x < 256) {
        int f = blockIdx.x;
        __shared__ float s_w[4];
        float2 v = *(const float2*)&Wv[f*AD + t*2];
        float s = warp_sum(v.x + v.y);
        if (l == 0) s_w[w] = s;
        __syncthreads();
        if (t == 0) d_wvsum[f] = s_w[0] + s_w[1] + s_w[2] + s_w[3];
        return;
    }

    __shared__ float red[128];
    int c = t >> 1;
    int j = t & 1;
    float we = 0.f;
    #pragma unroll
    for (int i = 0; i < 16; i++) {
        float4 a = *(const float4*)&Wpt[c*PD + j*64 + i*4];
        float4 b = *(const float4*)&Wph[j*64 + i*4];
        we += a.x*b.x + a.y*b.y + a.z*b.z + a.w*b.w;
    }
    we += __shfl_xor_sync(0xffffffffu, we, 1);
    if (j == 0) d_gw[c] = gp[c] * we;

    float v_sgw = (j == 0) ? gp[c] * we : 0.f;
    float v_bc  = (j == 0) ? bp[c] * we : 0.f;
    float v_bpt = bpt[t] * Wph[t];

    red[t] = v_sgw; __syncthreads();
    #pragma unroll
    for (int o = 64; o > 0; o >>= 1) { if (t < o) red[t] += red[t+o]; __syncthreads(); }
    if (t == 0) d_sgw = red[0];
    __syncthreads();
    red[t] = v_bc + v_bpt; __syncthreads();
    #pragma unroll
    for (int o = 64; o > 0; o >>= 1) { if (t < o) red[t] += red[t+o]; __syncthreads(); }
    if (t == 0) d_bconst = red[0];
}

// ---------------- K0: M = Wq @ Wk^T  (256x256, K=256, NT) -------------------
__global__ void __launch_bounds__(256)
mgemm_kernel(const float* __restrict__ Wq, const float* __restrict__ Wk) {
    __shared__ float As[16][68];
    __shared__ float Bs[16][68];
    int f0 = blockIdx.y * 64;
    int g0 = blockIdx.x * 64;
    int tid = threadIdx.x;
    int lm = tid >> 2;
    int lk = (tid & 3) * 4;
    int ty = tid >> 4, tx = tid & 15;

    float acc[4][4] = {};
    for (int kt = 0; kt < AD; kt += 16) {
        float4 a = *(const float4*)&Wq[(f0 + lm)*AD + kt + lk];
        As[lk+0][lm] = a.x; As[lk+1][lm] = a.y;
        As[lk+2][lm] = a.z; As[lk+3][lm] = a.w;
        float4 c = *(const float4*)&Wk[(g0 + lm)*AD + kt + lk];
        Bs[lk+0][lm] = c.x; Bs[lk+1][lm] = c.y;
        Bs[lk+2][lm] = c.z; Bs[lk+3][lm] = c.w;
        __syncthreads();
        #pragma unroll
        for (int kf = 0; kf < 16; kf++) {
            float4 av = *(const float4*)&As[kf][ty*4];
            float4 bv = *(const float4*)&Bs[kf][tx*4];
            float aa[4] = {av.x, av.y, av.z, av.w};
            float bb[4] = {bv.x, bv.y, bv.z, bv.w};
            #pragma unroll
            for (int i = 0; i < 4; i++)
                #pragma unroll
                for (int j = 0; j < 4; j++)
                    acc[i][j] += aa[i] * bb[j];
        }
        __syncthreads();
    }
    #pragma unroll
    for (int i = 0; i < 4; i++)
        #pragma unroll
        for (int j = 0; j < 4; j++)
            d_M[(f0 + ty*4 + i)*FD + g0 + tx*4 + j] = acc[i][j];
}

// ---------------- K2: LayerNorm(F) -> Fn, vsum ------------------------------
__global__ void __launch_bounds__(256)
lnf_kernel(const float* __restrict__ F,
           const float* __restrict__ gf,
           const float* __restrict__ bf) {
    __shared__ float s_a[8], s_b[8];
    int r = blockIdx.x;
    int t = threadIdx.x;
    int w = t >> 5, l = t & 31;
    float x = F[r*FD + t];

    float sa = warp_sum(x);
    float sb = warp_sum(x*x);
    if (l == 0) { s_a[w] = sa; s_b[w] = sb; }
    __syncthreads();
    float ts = 0.f, tq = 0.f;
    #pragma unroll
    for (int i = 0; i < 8; i++) { ts += s_a[i]; tq += s_b[i]; }
    float mu = ts * (1.f/FD);
    float rstd = rsqrtf(tq * (1.f/FD) - mu*mu + EPSF);
    float fn = (x - mu) * rstd * gf[t] + bf[t];
    d_Fn[r*FD + t] = fn;

    __syncthreads();
    float sv = warp_sum(fn * d_wvsum[t]);
    if (l == 0) s_a[w] = sv;
    __syncthreads();
    if (t == 0) {
        float acc = 0.f;
        #pragma unroll
        for (int i = 0; i < 8; i++) acc += s_a[i];
        d_vsum[r] = acc;
    }
}

// ---------------- K3: fused  T = Fn @ M (first)  ||  bias(D sweep) ----------
// 32-reg cap: 8 resident blocks (64 warps) for the latency-bound bias sweep.
// The T branch may spill slightly; its 128 blocks hide under the sweep.
__global__ void __launch_bounds__(256, 8)
bias_t_kernel(const float* __restrict__ Dm) {
    int tid = threadIdx.x;

    if (blockIdx.x >= T_TILES) {
        int w = tid >> 5, l = tid & 31;
        int sub = l & 7;          // column group: 2 float4 slots (32B)
        int rr  = l >> 3;         // row within group of 4

        float4 g0 = *(const float4*)&d_gw[sub*8];
        float4 g1 = *(const float4*)&d_gw[sub*8 + 4];
        float sgw = d_sgw, bconst = d_bconst;

        int rowbase = (blockIdx.x - T_TILES) * 256 + w * 32 + rr;
        #pragma unroll
        for (int it = 0; it < 8; it++) {
            int row = rowbase + it * 4;
            const float4* p = (const float4*)&Dm[(size_t)row * DP];
            float4 c0 = __ldcs(p + sub*2);
            float4 c1 = __ldcs(p + sub*2 + 1);

            float s1 = (c0.x+c0.y+c0.z+c0.w) + (c1.x+c1.y+c1.z+c1.w);
            float s2 = c0.x*c0.x+c0.y*c0.y+c0.z*c0.z+c0.w*c0.w
                     + c1.x*c1.x+c1.y*c1.y+c1.z*c1.z+c1.w*c1.w;
            float s3 = c0.x*g0.x+c0.y*g0.y+c0.z*g0.z+c0.w*g0.w
                     + c1.x*g1.x+c1.y*g1.y+c1.z*g1.z+c1.w*g1.w;

            #pragma unroll
            for (int o = 1; o < 8; o <<= 1) {
                s1 += __shfl_xor_sync(0xffffffffu, s1, o);
                s2 += __shfl_xor_sync(0xffffffffu, s2, o);
                s3 += __shfl_xor_sync(0xffffffffu, s3, o);
            }
            if (sub == 0) {
                float mu = s1 * (1.f/DP);
                float var = s2 * (1.f/DP) - mu*mu;
                float rstd = rsqrtf(var + EPSF);
                d_bias[row] = rstd * (s3 - mu*sgw) + bconst;
            }
        }
    } else {
        // ---- T[2048 x 256] = Fn[2048 x 256] @ M[256 x 256] (NN) ----
        __shared__ float As[16][68];
        __shared__ float Bs[16][68];
        int t2 = blockIdx.x;
        int bm = t2 & 31;
        int bn = t2 >> 5;
        int row0 = bm * 64;
        int n0   = bn * 64;

        int lm = tid >> 2;
        int lk = (tid & 3) * 4;
        int bk = tid >> 4;
        int bn4 = (tid & 15) * 4;
        int ty = tid >> 4, tx = tid & 15;

        float acc[4][4] = {};
        for (int kt = 0; kt < FD; kt += 16) {
            float4 a = *(const float4*)&d_Fn[(row0 + lm)*FD + kt + lk];
            As[lk+0][lm] = a.x; As[lk+1][lm] = a.y;
            As[lk+2][lm] = a.z; As[lk+3][lm] = a.w;
            float4 b = *(const float4*)&d_M[(kt + bk)*FD + n0 + bn4];
            Bs[bk][bn4+0] = b.x; Bs[bk][bn4+1] = b.y;
            Bs[bk][bn4+2] = b.z; Bs[bk][bn4+3] = b.w;
            __syncthreads();
            #pragma unroll
            for (int kf = 0; kf < 16; kf++) {
                float4 av = *(const float4*)&As[kf][ty*4];
                float4 bv = *(const float4*)&Bs[kf][tx*4];
                float aa[4] = {av.x, av.y, av.z, av.w};
                float bb[4] = {bv.x, bv.y, bv.z, bv.w};
                #pragma unroll
                for (int i = 0; i < 4; i++)
                    #pragma unroll
                    for (int j = 0; j < 4; j++)
                        acc[i][j] += aa[i] * bb[j];
            }
            __syncthreads();
        }
        #pragma unroll
        for (int i = 0; i < 4; i++) {
            int r = row0 + ty*4 + i;
            #pragma unroll
            for (int j = 0; j < 4; j++)
                d_T[r*FD + n0 + tx*4 + j] = acc[i][j];
        }
    }
}

// ---------------- K4: split-K S-GEMM, 128x128 block / 8x8 register tile -----
__global__ void __launch_bounds__(256)
s_gemm_kernel() {
    __shared__ float As[8][132];   // row stride 528B (16B-multiple)
    __shared__ float Bs[8][132];
    int z  = blockIdx.z;
    int b  = z >> 1;
    int half = z & 1;
    int q0 = blockIdx.y * 128;
    int k0 = blockIdx.x * 128;
    const float* A  = d_T  + b*NN*FD;
    const float* Bm = d_Fn + b*NN*FD;
    float* Sp = half ? d_Sb : d_Sa;

    int tid = threadIdx.x;
    int lrow = tid >> 1;            // 0..127
    int lk4  = (tid & 1) * 4;       // 0 or 4
    int ty = tid >> 4, tx = tid & 15;

    int kbase = half * 128;
    float acc[8][8] = {};

    float4 pa = *(const float4*)&A [(q0 + lrow)*FD + kbase + lk4];
    float4 pb = *(const float4*)&Bm[(k0 + lrow)*FD + kbase + lk4];

    for (int c = 0; c < 16; c++) {
        As[lk4+0][lrow] = pa.x; As[lk4+1][lrow] = pa.y;
        As[lk4+2][lrow] = pa.z; As[lk4+3][lrow] = pa.w;
        Bs[lk4+0][lrow] = pb.x; Bs[lk4+1][lrow] = pb.y;
        Bs[lk4+2][lrow] = pb.z; Bs[lk4+3][lrow] = pb.w;
        __syncthreads();
        if (c < 15) {
            int kt = kbase + (c + 1) * 8;
            pa = *(const float4*)&A [(q0 + lrow)*FD + kt + lk4];
            pb = *(const float4*)&Bm[(k0 + lrow)*FD + kt + lk4];
        }
        #pragma unroll
        for (int k = 0; k < 8; k++) {
            float a[8], bt[8];
            *(float4*)&a[0]  = *(const float4*)&As[k][ty*8];
            *(float4*)&a[4]  = *(const float4*)&As[k][ty*8 + 4];
            *(float4*)&bt[0] = *(const float4*)&Bs[k][tx*8];
            *(float4*)&bt[4] = *(const float4*)&Bs[k][tx*8 + 4];
            #pragma unroll
            for (int i = 0; i < 8; i++)
                #pragma unroll
                for (int j = 0; j < 8; j++)
                    acc[i][j] += a[i] * bt[j];
        }
        __syncthreads();
    }
    #pragma unroll
    for (int i = 0; i < 8; i++) {
        int q = q0 + ty*8 + i;
        int idx = (b*NN + q)*NN + k0 + tx*8;
        float4 o0, o1;
        o0.x = acc[i][0]; o0.y = acc[i][1]; o0.z = acc[i][2]; o0.w = acc[i][3];
        o1.x = acc[i][4]; o1.y = acc[i][5]; o1.z = acc[i][6]; o1.w = acc[i][7];
        *(float4*)&Sp[idx]     = o0;
        *(float4*)&Sp[idx + 4] = o1;
    }
}

// ---------------- K5: combine + softmax + dot with vsum ---------------------
__global__ void __launch_bounds__(256)
softmax_out_kernel(float* __restrict__ out) {
    __shared__ float s_a[8], s_b[8];
    int r = blockIdx.x;
    int b = r >> 9;
    int t = threadIdx.x;
    int w = t >> 5, l = t & 31;

    int i0 = r*NN + t, i1 = r*NN + 256 + t;
    float s0 = SCAL * (d_Sa[i0] + d_Sb[i0] + d_bias[i0]);
    float s1 = SCAL * (d_Sa[i1] + d_Sb[i1] + d_bias[i1]);
    float wm = warp_max(fmaxf(s0, s1));
    if (l == 0) s_a[w] = wm;
    __syncthreads();
    float m = s_a[0];
    #pragma unroll
    for (int i = 1; i < 8; i++) m = fmaxf(m, s_a[i]);

    float e0 = __expf(s0 - m), e1 = __expf(s1 - m);
    float v0 = d_vsum[b*NN + t], v1 = d_vsum[b*NN + 256 + t];
    __syncthreads();
    float se = warp_sum(e0 + e1);
    float sv = warp_sum(e0*v0 + e1*v1);
    if (l == 0) { s_a[w] = se; s_b[w] = sv; }
    __syncthreads();
    if (t == 0) {
        float tse = 0.f, tsv = 0.f;
        #pragma unroll
        for (int i = 0; i < 8; i++) { tse += s_a[i]; tsv += s_b[i]; }
        out[r] = tsv / tse;
    }
}

// ---------------- launch ----------------------------------------------------
extern "C" void kernel_launch(void* const* d_in, const int* in_sizes, int n_in,
                              void* d_out, int out_size) {
    const float* F   = (const float*)d_in[0];
    const float* Dm  = (const float*)d_in[1];
    const float* Wq  = (const float*)d_in[2];
    const float* Wk  = (const float*)d_in[3];
    const float* Wv  = (const float*)d_in[4];
    const float* gf  = (const float*)d_in[5];
    const float* bf  = (const float*)d_in[6];
    const float* gp  = (const float*)d_in[7];
    const float* bp  = (const float*)d_in[8];
    const float* Wpt = (const float*)d_in[9];
    const float* bpt = (const float*)d_in[10];
    const float* Wph = (const float*)d_in[11];
    float* out = (float*)d_out;

    mgemm_kernel<<<dim3(4, 4), 256>>>(Wq, Wk);
    prep_kernel<<<257, 128>>>(Wv, gp, bp, Wpt, bpt, Wph);
    lnf_kernel<<<ROWS, 256>>>(F, gf, bf);
    bias_t_kernel<<<T_TILES + BIAS_BLOCKS, 256>>>(Dm);
    dim3 g4(4, 4, BB*2);
    s_gemm_kernel<<<g4, 256>>>();
    softmax_out_kernel<<<ROWS, 256>>>(out);
}

// round 14
// speedup vs baseline: 1.2297x; 1.0481x over previous
#include <cuda_runtime.h>

#define BB   4
#define NN   512
#define FD   256
#define AD   256
#define DP   64
#define PD   128
#define ROWS (BB*NN)          /* 2048 */
#define NPAIR (BB*NN*NN)      /* 1048576 */
#define EPSF 1e-3f
#define SCAL 0.0625f          /* 1/sqrt(256) */

#define BIAS_BLOCKS 4096      /* 1048576 rows / 256 rows per block */
#define T_TILES     128       /* (2048/64) * (256/64) */

// ---------------- scratch (device globals; no allocation allowed) ----------
__device__ float d_Fn[ROWS*FD];
__device__ float d_M[FD*FD];         // Wq @ Wk^T
__device__ float d_T[ROWS*FD];       // Fn @ M
__device__ float d_vsum[ROWS];
__device__ float d_gw[DP];
__device__ float d_sgw;
__device__ float d_bconst;
__device__ float d_wvsum[FD];
__device__ float d_bias[NPAIR];
__device__ float d_Sa[NPAIR];        // split-K partial (K 0..127)
__device__ float d_Sb[NPAIR];        // split-K partial (K 128..255)

// ---------------- helpers ---------------------------------------------------
__device__ __forceinline__ float warp_sum(float v) {
    #pragma unroll
    for (int o = 16; o > 0; o >>= 1) v += __shfl_xor_sync(0xffffffffu, v, o);
    return v;
}
__device__ __forceinline__ float warp_max(float v) {
    #pragma unroll
    for (int o = 16; o > 0; o >>= 1) v = fmaxf(v, __shfl_xor_sync(0xffffffffu, v, o));
    return v;
}
__device__ __forceinline__ unsigned long long pack2(float lo, float hi) {
    unsigned long long r;
    asm("mov.b64 %0, {%1, %2};" : "=l"(r) : "f"(lo), "f"(hi));
    return r;
}
__device__ __forceinline__ void ffma2(unsigned long long& d,
                                      unsigned long long a,
                                      unsigned long long b) {
    asm("fma.rn.f32x2 %0, %1, %2, %0;" : "+l"(d) : "l"(a), "l"(b));
}
__device__ __forceinline__ float2 unpack2(unsigned long long v) {
    float2 f;
    asm("mov.b64 {%0, %1}, %2;" : "=f"(f.x), "=f"(f.y) : "l"(v));
    return f;
}

// ---------------- K1: prep + mgemm  (grid 273 x 256) ------------------------
__global__ void __launch_bounds__(256)
prep_mgemm_kernel(const float* __restrict__ Wq,
                  const float* __restrict__ Wk,
                  const float* __restrict__ Wv,
                  const float* __restrict__ gp,
                  const float* __restrict__ bp,
                  const float* __restrict__ Wpt,
                  const float* __restrict__ bpt,
                  const float* __restrict__ Wph) {
    int tid = threadIdx.x;

    if (blockIdx.x < 16) {
        __shared__ float As[16][68];
        __shared__ float Bs[16][68];
        int f0 = (blockIdx.x >> 2) * 64;
        int g0 = (blockIdx.x & 3) * 64;
        int lm = tid >> 2;
        int lk = (tid & 3) * 4;
        int ty = tid >> 4, tx = tid & 15;

        float acc[4][4] = {};
        for (int kt = 0; kt < AD; kt += 16) {
            float4 a = *(const float4*)&Wq[(f0 + lm)*AD + kt + lk];
            As[lk+0][lm] = a.x; As[lk+1][lm] = a.y;
            As[lk+2][lm] = a.z; As[lk+3][lm] = a.w;
            float4 c = *(const float4*)&Wk[(g0 + lm)*AD + kt + lk];
            Bs[lk+0][lm] = c.x; Bs[lk+1][lm] = c.y;
            Bs[lk+2][lm] = c.z; Bs[lk+3][lm] = c.w;
            __syncthreads();
            #pragma unroll
            for (int kf = 0; kf < 16; kf++) {
                float4 av = *(const float4*)&As[kf][ty*4];
                float4 bv = *(const float4*)&Bs[kf][tx*4];
                float aa[4] = {av.x, av.y, av.z, av.w};
                float bb[4] = {bv.x, bv.y, bv.z, bv.w};
                #pragma unroll
                for (int i = 0; i < 4; i++)
                    #pragma unroll
                    for (int j = 0; j < 4; j++)
                        acc[i][j] += aa[i] * bb[j];
            }
            __syncthreads();
        }
        #pragma unroll
        for (int i = 0; i < 4; i++)
            #pragma unroll
            for (int j = 0; j < 4; j++)
                d_M[(f0 + ty*4 + i)*FD + g0 + tx*4 + j] = acc[i][j];
    } else if (blockIdx.x < 272) {
        int f = blockIdx.x - 16;
        __shared__ float s_w[8];
        int w = tid >> 5, l = tid & 31;
        float s = warp_sum(Wv[f*AD + tid]);
        if (l == 0) s_w[w] = s;
        __syncthreads();
        if (tid == 0) {
            float acc = 0.f;
            #pragma unroll
            for (int i = 0; i < 8; i++) acc += s_w[i];
            d_wvsum[f] = acc;
        }
    } else {
        __shared__ float red[256];
        int c = tid >> 1;
        int j = tid & 1;
        float we = 0.f;
        if (tid < 128) {
            #pragma unroll
            for (int i = 0; i < 16; i++) {
                float4 a = *(const float4*)&Wpt[c*PD + j*64 + i*4];
                float4 b = *(const float4*)&Wph[j*64 + i*4];
                we += a.x*b.x + a.y*b.y + a.z*b.z + a.w*b.w;
            }
            we += __shfl_xor_sync(0xffffffffu, we, 1);
            if (j == 0) d_gw[c] = gp[c] * we;
        }
        float v_sgw = (tid < 128 && j == 0) ? gp[c] * we : 0.f;
        float v_bc  = (tid < 128 && j == 0) ? bp[c] * we : 0.f;
        float v_bpt = (tid < 128) ? bpt[tid] * Wph[tid] : 0.f;

        red[tid] = v_sgw; __syncthreads();
        #pragma unroll
        for (int o = 128; o > 0; o >>= 1) { if (tid < o) red[tid] += red[tid+o]; __syncthreads(); }
        if (tid == 0) d_sgw = red[0];
        __syncthreads();
        red[tid] = v_bc + v_bpt; __syncthreads();
        #pragma unroll
        for (int o = 128; o > 0; o >>= 1) { if (tid < o) red[tid] += red[tid+o]; __syncthreads(); }
        if (tid == 0) d_bconst = red[0];
    }
}

// ---------------- K2: LayerNorm(F) -> Fn, vsum ------------------------------
__global__ void __launch_bounds__(256)
lnf_kernel(const float* __restrict__ F,
           const float* __restrict__ gf,
           const float* __restrict__ bf) {
    __shared__ float s_a[8], s_b[8];
    int r = blockIdx.x;
    int t = threadIdx.x;
    int w = t >> 5, l = t & 31;
    float x = F[r*FD + t];

    float sa = warp_sum(x);
    float sb = warp_sum(x*x);
    if (l == 0) { s_a[w] = sa; s_b[w] = sb; }
    __syncthreads();
    float ts = 0.f, tq = 0.f;
    #pragma unroll
    for (int i = 0; i < 8; i++) { ts += s_a[i]; tq += s_b[i]; }
    float mu = ts * (1.f/FD);
    float rstd = rsqrtf(tq * (1.f/FD) - mu*mu + EPSF);
    float fn = (x - mu) * rstd * gf[t] + bf[t];
    d_Fn[r*FD + t] = fn;

    __syncthreads();
    float sv = warp_sum(fn * d_wvsum[t]);
    if (l == 0) s_a[w] = sv;
    __syncthreads();
    if (t == 0) {
        float acc = 0.f;
        #pragma unroll
        for (int i = 0; i < 8; i++) acc += s_a[i];
        d_vsum[r] = acc;
    }
}

// ---------------- K3: fused  T = Fn @ M (first)  ||  bias(D sweep) ----------
__global__ void __launch_bounds__(256, 8)
bias_t_kernel(const float* __restrict__ Dm) {
    int tid = threadIdx.x;

    if (blockIdx.x >= T_TILES) {
        int w = tid >> 5, l = tid & 31;
        int sub = l & 7;          // column group: 2 float4 slots (32B)
        int rr  = l >> 3;         // row within group of 4

        float4 g0 = *(const float4*)&d_gw[sub*8];
        float4 g1 = *(const float4*)&d_gw[sub*8 + 4];
        float sgw = d_sgw, bconst = d_bconst;

        int rowbase = (blockIdx.x - T_TILES) * 256 + w * 32 + rr;
        #pragma unroll
        for (int it = 0; it < 8; it++) {
            int row = rowbase + it * 4;
            const float4* p = (const float4*)&Dm[(size_t)row * DP];
            float4 c0 = __ldcs(p + sub*2);
            float4 c1 = __ldcs(p + sub*2 + 1);

            float s1 = (c0.x+c0.y+c0.z+c0.w) + (c1.x+c1.y+c1.z+c1.w);
            float s2 = c0.x*c0.x+c0.y*c0.y+c0.z*c0.z+c0.w*c0.w
                     + c1.x*c1.x+c1.y*c1.y+c1.z*c1.z+c1.w*c1.w;
            float s3 = c0.x*g0.x+c0.y*g0.y+c0.z*g0.z+c0.w*g0.w
                     + c1.x*g1.x+c1.y*g1.y+c1.z*g1.z+c1.w*g1.w;

            #pragma unroll
            for (int o = 1; o < 8; o <<= 1) {
                s1 += __shfl_xor_sync(0xffffffffu, s1, o);
                s2 += __shfl_xor_sync(0xffffffffu, s2, o);
                s3 += __shfl_xor_sync(0xffffffffu, s3, o);
            }
            if (sub == 0) {
                float mu = s1 * (1.f/DP);
                float var = s2 * (1.f/DP) - mu*mu;
                float rstd = rsqrtf(var + EPSF);
                d_bias[row] = rstd * (s3 - mu*sgw) + bconst;
            }
        }
    } else {
        // ---- T[2048 x 256] = Fn[2048 x 256] @ M[256 x 256] (NN) ----
        __shared__ float As[16][68];
        __shared__ float Bs[16][68];
        int t2 = blockIdx.x;
        int bm = t2 & 31;
        int bn = t2 >> 5;
        int row0 = bm * 64;
        int n0   = bn * 64;

        int lm = tid >> 2;
        int lk = (tid & 3) * 4;
        int bk = tid >> 4;
        int bn4 = (tid & 15) * 4;
        int ty = tid >> 4, tx = tid & 15;

        float acc[4][4] = {};
        for (int kt = 0; kt < FD; kt += 16) {
            float4 a = *(const float4*)&d_Fn[(row0 + lm)*FD + kt + lk];
            As[lk+0][lm] = a.x; As[lk+1][lm] = a.y;
            As[lk+2][lm] = a.z; As[lk+3][lm] = a.w;
            float4 b = *(const float4*)&d_M[(kt + bk)*FD + n0 + bn4];
            Bs[bk][bn4+0] = b.x; Bs[bk][bn4+1] = b.y;
            Bs[bk][bn4+2] = b.z; Bs[bk][bn4+3] = b.w;
            __syncthreads();
            #pragma unroll
            for (int kf = 0; kf < 16; kf++) {
                float4 av = *(const float4*)&As[kf][ty*4];
                float4 bv = *(const float4*)&Bs[kf][tx*4];
                float aa[4] = {av.x, av.y, av.z, av.w};
                float bb[4] = {bv.x, bv.y, bv.z, bv.w};
                #pragma unroll
                for (int i = 0; i < 4; i++)
                    #pragma unroll
                    for (int j = 0; j < 4; j++)
                        acc[i][j] += aa[i] * bb[j];
            }
            __syncthreads();
        }
        #pragma unroll
        for (int i = 0; i < 4; i++) {
            int r = row0 + ty*4 + i;
            #pragma unroll
            for (int j = 0; j < 4; j++)
                d_T[r*FD + n0 + tx*4 + j] = acc[i][j];
        }
    }
}

// ---------------- K4: split-K S-GEMM, 128x128 / 8x8 tile, packed f32x2 ------
__global__ void __launch_bounds__(256)
s_gemm_kernel() {
    __shared__ float As[8][132];   // row stride 528B (16B-multiple)
    __shared__ float Bs[8][132];
    int z  = blockIdx.z;
    int b  = z >> 1;
    int half = z & 1;
    int q0 = blockIdx.y * 128;
    int k0 = blockIdx.x * 128;
    const float* A  = d_T  + b*NN*FD;
    const float* Bm = d_Fn + b*NN*FD;
    float* Sp = half ? d_Sb : d_Sa;

    int tid = threadIdx.x;
    int lrow = tid >> 1;            // 0..127
    int lk4  = (tid & 1) * 4;       // 0 or 4
    int ty = tid >> 4, tx = tid & 15;

    int kbase = half * 128;
    unsigned long long acc2[8][4] = {};   // (i, j-pair) packed f32x2

    float4 pa = *(const float4*)&A [(q0 + lrow)*FD + kbase + lk4];
    float4 pb = *(const float4*)&Bm[(k0 + lrow)*FD + kbase + lk4];

    for (int c = 0; c < 16; c++) {
        As[lk4+0][lrow] = pa.x; As[lk4+1][lrow] = pa.y;
        As[lk4+2][lrow] = pa.z; As[lk4+3][lrow] = pa.w;
        Bs[lk4+0][lrow] = pb.x; Bs[lk4+1][lrow] = pb.y;
        Bs[lk4+2][lrow] = pb.z; Bs[lk4+3][lrow] = pb.w;
        __syncthreads();
        if (c < 15) {
            int kt = kbase + (c + 1) * 8;
            pa = *(const float4*)&A [(q0 + lrow)*FD + kt + lk4];
            pb = *(const float4*)&Bm[(k0 + lrow)*FD + kt + lk4];
        }
        #pragma unroll
        for (int k = 0; k < 8; k++) {
            float a[8], bt[8];
            *(float4*)&a[0]  = *(const float4*)&As[k][ty*8];
            *(float4*)&a[4]  = *(const float4*)&As[k][ty*8 + 4];
            *(float4*)&bt[0] = *(const float4*)&Bs[k][tx*8];
            *(float4*)&bt[4] = *(const float4*)&Bs[k][tx*8 + 4];
            unsigned long long bp[4];
            #pragma unroll
            for (int j2 = 0; j2 < 4; j2++) bp[j2] = pack2(bt[2*j2], bt[2*j2+1]);
            #pragma unroll
            for (int i = 0; i < 8; i++) {
                unsigned long long ap = pack2(a[i], a[i]);
                #pragma unroll
                for (int j2 = 0; j2 < 4; j2++) ffma2(acc2[i][j2], ap, bp[j2]);
            }
        }
        __syncthreads();
    }
    #pragma unroll
    for (int i = 0; i < 8; i++) {
        int q = q0 + ty*8 + i;
        int idx = (b*NN + q)*NN + k0 + tx*8;
        float2 p0 = unpack2(acc2[i][0]);
        float2 p1 = unpack2(acc2[i][1]);
        float2 p2 = unpack2(acc2[i][2]);
        float2 p3 = unpack2(acc2[i][3]);
        float4 o0, o1;
        o0.x = p0.x; o0.y = p0.y; o0.z = p1.x; o0.w = p1.y;
        o1.x = p2.x; o1.y = p2.y; o1.z = p3.x; o1.w = p3.y;
        *(float4*)&Sp[idx]     = o0;
        *(float4*)&Sp[idx + 4] = o1;
    }
}

// ---------------- K5: softmax, one warp per row -----------------------------
// grid 256 x 256 threads: row = blockIdx.x*8 + warp; lane owns 16 cols.
__global__ void __launch_bounds__(256)
softmax_out_kernel(float* __restrict__ out) {
    int wid = threadIdx.x >> 5, l = threadIdx.x & 31;
    int r = blockIdx.x * 8 + wid;
    int b = r >> 9;

    float s[16];
    #pragma unroll
    for (int c = 0; c < 4; c++) {
        int idx = r*NN + c*128 + l*4;
        float4 xa = *(const float4*)&d_Sa[idx];
        float4 xb = *(const float4*)&d_Sb[idx];
        float4 xc = *(const float4*)&d_bias[idx];
        s[c*4+0] = SCAL * (xa.x + xb.x + xc.x);
        s[c*4+1] = SCAL * (xa.y + xb.y + xc.y);
        s[c*4+2] = SCAL * (xa.z + xb.z + xc.z);
        s[c*4+3] = SCAL * (xa.w + xb.w + xc.w);
    }
    float m = s[0];
    #pragma unroll
    for (int i = 1; i < 16; i++) m = fmaxf(m, s[i]);
    m = warp_max(m);

    float se = 0.f, sv = 0.f;
    #pragma unroll
    for (int c = 0; c < 4; c++) {
        float4 vv = *(const float4*)&d_vsum[b*NN + c*128 + l*4];
        float e0 = __expf(s[c*4+0] - m);
        float e1 = __expf(s[c*4+1] - m);
        float e2 = __expf(s[c*4+2] - m);
        float e3 = __expf(s[c*4+3] - m);
        se += e0 + e1 + e2 + e3;
        sv += e0*vv.x + e1*vv.y + e2*vv.z + e3*vv.w;
    }
    se = warp_sum(se);
    sv = warp_sum(sv);
    if (l == 0) out[r] = sv / se;
}

// ---------------- launch ----------------------------------------------------
extern "C" void kernel_launch(void* const* d_in, const int* in_sizes, int n_in,
                              void* d_out, int out_size) {
    const float* F   = (const float*)d_in[0];
    const float* Dm  = (const float*)d_in[1];
    const float* Wq  = (const float*)d_in[2];
    const float* Wk  = (const float*)d_in[3];
    const float* Wv  = (const float*)d_in[4];
    const float* gf  = (const float*)d_in[5];
    const float* bf  = (const float*)d_in[6];
    const float* gp  = (const float*)d_in[7];
    const float* bp  = (const float*)d_in[8];
    const float* Wpt = (const float*)d_in[9];
    const float* bpt = (const float*)d_in[10];
    const float* Wph = (const float*)d_in[11];
    float* out = (float*)d_out;

    prep_mgemm_kernel<<<273, 256>>>(Wq, Wk, Wv, gp, bp, Wpt, bpt, Wph);
    lnf_kernel<<<ROWS, 256>>>(F, gf, bf);
    bias_t_kernel<<<T_TILES + BIAS_BLOCKS, 256>>>(Dm);
    dim3 g4(4, 4, BB*2);
    s_gemm_kernel<<<g4, 256>>>();
    softmax_out_kernel<<<ROWS/8, 256>>>(out);
}